// round 17
// baseline (speedup 1.0000x reference)
#include <cuda_runtime.h>
#include <cuda_bf16.h>
#include <stdint.h>
#include <math.h>

#define B_   32
#define C_   256
#define HH   56
#define WW   56
#define E_   4
#define O_   256
#define HID_ 64
#define NPIX 3136
#define KDIM 2304
#define WPERB (O_*KDIM)
#define BK   32
#define NKT  (KDIM/BK)                // 72 k-tiles
#define PIMG 3364                     // 58*58 padded plane
#define KROW 136                      // packed stride (floats) for A and B
#define ASTG (BK*KROW)                // 4352 floats per stage (A and B alike)
#define BN   128                      // CTA n tile
#define NTILES 25                     // ceil(3136/128)

// ---------------- device scratch (no runtime allocation) ----------------
__device__ float g_routing[B_*E_];
__device__ float g_pooled[B_*C_];
__device__ int   g_ktab[KDIM];
// A tf32, k-major packed blocks: [b][tile_m(2)][kt(72)] -> [k(32)][m(136 pad)]
__device__ __align__(16) float g_combined[(size_t)B_*2*NKT*ASTG];
__device__ __align__(16) float g_xpad[(size_t)B_*C_*PIMG + 4096]; // padded tf32 x

// ---------------- helpers ----------------
__device__ __forceinline__ uint32_t f2tf32(float f) {
    uint32_t u;
    asm("cvt.rna.tf32.f32 %0, %1;" : "=r"(u) : "f"(f));
    return u;
}

__device__ __forceinline__ void mma_tf32(float* d, const uint32_t* a, uint32_t b0, uint32_t b1) {
    asm volatile(
        "mma.sync.aligned.m16n8k8.row.col.f32.tf32.tf32.f32 "
        "{%0,%1,%2,%3}, {%4,%5,%6,%7}, {%8,%9}, {%0,%1,%2,%3};"
        : "+f"(d[0]), "+f"(d[1]), "+f"(d[2]), "+f"(d[3])
        : "r"(a[0]), "r"(a[1]), "r"(a[2]), "r"(a[3]), "r"(b0), "r"(b1));
}

#define CP_ASYNC16(dst_u32, src_ptr) \
    asm volatile("cp.async.cg.shared.global [%0], [%1], 16;" :: "r"(dst_u32), "l"(src_ptr))
#define CP_ASYNC4(dst_u32, src_ptr) \
    asm volatile("cp.async.ca.shared.global [%0], [%1], 4;" :: "r"(dst_u32), "l"(src_ptr))
#define CP_COMMIT() asm volatile("cp.async.commit_group;" ::: "memory")
#define CP_WAIT0()  asm volatile("cp.async.wait_group 0;"  ::: "memory")

// ===========================================================================
// Kernel 1a: fused zero-pad + tf32-round + global average pool.
// ===========================================================================
__global__ void __launch_bounds__(128) pad_pool_kernel(const float* __restrict__ x) {
    const int c = blockIdx.x, b = blockIdx.y;
    const int tid = threadIdx.x;
    const float* src = x + ((size_t)b*C_ + c)*NPIX;
    float* dst = g_xpad + ((size_t)b*C_ + c)*PIMG;

    float s = 0.f;
    for (int idx = tid; idx < PIMG; idx += 128) {
        const int py = idx / 58;
        const int px = idx - py*58;
        float v = 0.f;
        if ((unsigned)(py-1) < 56u && (unsigned)(px-1) < 56u) {
            v = src[(py-1)*WW + (px-1)];
            s += v;
        }
        dst[idx] = __uint_as_float(f2tf32(v));
    }
    #pragma unroll
    for (int o = 16; o; o >>= 1) s += __shfl_xor_sync(0xffffffffu, s, o);
    __shared__ float ws[4];
    if ((tid & 31) == 0) ws[tid >> 5] = s;
    __syncthreads();
    if (tid == 0) g_pooled[b*C_ + c] = (ws[0]+ws[1]+ws[2]+ws[3]) * (1.0f/(float)NPIX);
}

// ===========================================================================
// Kernel 1b: MLP + softmax routing. grid B_, 64 threads. Block 0 also fills ktab.
// ===========================================================================
__global__ void __launch_bounds__(64) mlp_kernel(const float* __restrict__ rw1,
                                                 const float* __restrict__ rb1,
                                                 const float* __restrict__ rw2,
                                                 const float* __restrict__ rb2) {
    const int b = blockIdx.x, t = threadIdx.x;
    if (b == 0) {
        for (int k = t; k < KDIM; k += 64) {
            int c = k / 9, rem = k - 9*c;
            int ky = rem / 3 - 1, kx = rem % 3 - 1;
            g_ktab[k] = c*PIMG + ky*58 + kx;
        }
    }
    __shared__ float pl[C_];
    __shared__ float hid[HID_];
    __shared__ float logits[E_];
    for (int c = t; c < C_; c += 64) pl[c] = g_pooled[b*C_ + c];
    __syncthreads();
    {
        float s = rb1[t];
        const float* w = rw1 + t * C_;
        #pragma unroll 8
        for (int c = 0; c < C_; c++) s = fmaf(w[c], pl[c], s);
        hid[t] = fmaxf(s, 0.f);
    }
    __syncthreads();
    if (t < E_) {
        float s = rb2[t];
        const float* w = rw2 + t * HID_;
        #pragma unroll 8
        for (int h = 0; h < HID_; h++) s = fmaf(w[h], hid[h], s);
        logits[t] = s;
    }
    __syncthreads();
    if (t == 0) {
        float m = logits[0];
        #pragma unroll
        for (int e = 1; e < E_; e++) m = fmaxf(m, logits[e]);
        float ex[E_], sum = 0.f;
        #pragma unroll
        for (int e = 0; e < E_; e++) { ex[e] = expf(logits[e] - m); sum += ex[e]; }
        float inv = 1.0f / sum;
        #pragma unroll
        for (int e = 0; e < E_; e++) g_routing[b*E_ + e] = ex[e] * inv;
    }
}

// ===========================================================================
// Kernel 2: mix experts -> k-major packed tf32 A blocks [32][136].
//   grid (2*NKT, B_) = (144, 32), 256 threads, smem-staged transpose.
// ===========================================================================
__global__ void __launch_bounds__(256) combine_kernel(const float* __restrict__ experts) {
    __shared__ float st[128*33];
    const int b  = blockIdx.y;
    const int bx = blockIdx.x;                 // tile_m*NKT + kt
    const int tile_m = bx / NKT;
    const int kt = bx - tile_m*NKT;
    const int tid = threadIdx.x;

    const float r0 = g_routing[b*E_+0], r1 = g_routing[b*E_+1];
    const float r2 = g_routing[b*E_+2], r3 = g_routing[b*E_+3];

    // read 128 rows x 32 k: 1024 float4, coalesced (8 float4 per row)
    #pragma unroll
    for (int i = 0; i < 4; i++) {
        const int idx = tid + i*256;
        const int row = idx >> 3, c4 = idx & 7;
        const size_t base = (size_t)(tile_m*128 + row)*KDIM + kt*32 + c4*4;
        float4 a = *(const float4*)(experts + base);
        float4 c = *(const float4*)(experts + (size_t)WPERB   + base);
        float4 d = *(const float4*)(experts + (size_t)2*WPERB + base);
        float4 f = *(const float4*)(experts + (size_t)3*WPERB + base);
        float* dst = st + row*33 + c4*4;
        dst[0] = __uint_as_float(f2tf32(r0*a.x + r1*c.x + r2*d.x + r3*f.x));
        dst[1] = __uint_as_float(f2tf32(r0*a.y + r1*c.y + r2*d.y + r3*f.y));
        dst[2] = __uint_as_float(f2tf32(r0*a.z + r1*c.z + r2*d.z + r3*f.z));
        dst[3] = __uint_as_float(f2tf32(r0*a.w + r1*c.w + r2*d.w + r3*f.w));
    }
    __syncthreads();

    // transpose out: [k][136]; thread: k = tid>>3, m0 = (tid&7)*16 (coalesced)
    float* outp = g_combined + ((size_t)(b*2 + tile_m)*NKT + kt)*ASTG;
    const int k  = tid >> 3;
    const int m0 = (tid & 7) * 16;
    #pragma unroll
    for (int i = 0; i < 4; i++) {
        const float* s = st + (m0 + 4*i)*33 + k;
        float4 v = make_float4(s[0], s[33], s[66], s[99]);
        *(float4*)(outp + k*KROW + m0 + 4*i) = v;
    }
}

// ===========================================================================
// Kernel 3: TF32 mma.sync implicit-GEMM conv.
//   CTA 128(oc) x 128(px), 4 warps = 2(m) x 2(n), warp tile 64x64, 3 CTAs/SM.
//   A: linear cp.async of packed [32][136] blocks.
//   B: cp.async.ca 4B im2col gather -> [k32][n136] smem.
//   smem: 2*ASTG (A) + 2*ASTG (B) = 68 KB/CTA, 3 CTAs = 209 KB/SM.
// ===========================================================================
__global__ void __launch_bounds__(128, 3) conv_mma_kernel(float* __restrict__ out) {
    extern __shared__ float sm[];
    float* As = sm;                     // 2 * ASTG
    float* Bs = sm + 2*ASTG;            // 2 * ASTG

    const int tid    = threadIdx.x;
    const int lane   = tid & 31;
    const int warp   = tid >> 5;
    const int nBase  = blockIdx.x * BN;
    const int tile_m = blockIdx.y;
    const int b      = blockIdx.z;

    const int g  = lane >> 2;      // 0..7
    const int tg = lane & 3;       // 0..3
    const int wm = warp >> 1;      // 0..1 (m)
    const int wn = warp & 1;       // 0..1 (n)

    const float* Ab = g_combined + ((size_t)(b*2 + tile_m)*NKT)*ASTG;

    // B producer: each thread owns one pixel, 32 k gathers per tile
    const int n  = nBase + tid;
    const int ny = n / WW, nx = n - (n / WW) * WW;
    const float* xpb = g_xpad + (size_t)b*C_*PIMG + (ny+1)*58 + (nx+1);

    const uint32_t sb  = (uint32_t)__cvta_generic_to_shared(sm);
    const uint32_t sbB = sb + 2*ASTG*4u;

    // one tile: A linear 17 KB (9 cp.async16 rounds) + B (32 cp.async4)
    #define ISSUE(kt_, s) do {                                                       \
        const float* _as = Ab + (size_t)(kt_)*ASTG;                                  \
        _Pragma("unroll")                                                            \
        for (int i = 0; i < 9; i++) {                                                \
            int idx = tid + i*128;                                                   \
            if (idx < ASTG/4)                                                        \
                CP_ASYNC16(sb + (uint32_t)((s)*ASTG + idx*4)*4u, _as + idx*4);       \
        }                                                                            \
        {                                                                            \
            const int4* _t4 = (const int4*)(g_ktab + (kt_)*BK);                      \
            const uint32_t _d0 = sbB + (uint32_t)((s)*ASTG + tid)*4u;                \
            _Pragma("unroll")                                                        \
            for (int qq = 0; qq < 8; qq++) {                                         \
                int4 kv = _t4[qq];                                                   \
                CP_ASYNC4(_d0 + (qq*4+0)*KROW*4u, xpb + kv.x);                       \
                CP_ASYNC4(_d0 + (qq*4+1)*KROW*4u, xpb + kv.y);                       \
                CP_ASYNC4(_d0 + (qq*4+2)*KROW*4u, xpb + kv.z);                       \
                CP_ASYNC4(_d0 + (qq*4+3)*KROW*4u, xpb + kv.w);                       \
            }                                                                        \
        }                                                                            \
        CP_COMMIT();                                                                 \
    } while (0)

    #define COMPUTE_KS(ks) do {                                                      \
        uint32_t afr[4][4];                                                          \
        _Pragma("unroll")                                                            \
        for (int mi = 0; mi < 4; mi++) {                                             \
            const uint32_t* p = Aw + (ks)*(8*KROW) + mi*16;                          \
            afr[mi][0] = p[0];                                                       \
            afr[mi][1] = p[8];                                                       \
            afr[mi][2] = p[4*KROW];                                                  \
            afr[mi][3] = p[4*KROW + 8];                                              \
        }                                                                            \
        _Pragma("unroll")                                                            \
        for (int ni = 0; ni < 8; ni++) {                                             \
            const uint32_t* q = Bw + (ks)*(8*KROW) + ni*8;                           \
            uint32_t b0 = q[0], b1 = q[4*KROW];                                      \
            _Pragma("unroll")                                                        \
            for (int mi = 0; mi < 4; mi++)                                           \
                mma_tf32(acc[mi][ni], afr[mi], b0, b1);                              \
        }                                                                            \
    } while (0)

    float acc[4][8][4];
    #pragma unroll
    for (int mi = 0; mi < 4; mi++)
        #pragma unroll
        for (int ni = 0; ni < 8; ni++)
            #pragma unroll
            for (int qq = 0; qq < 4; qq++) acc[mi][ni][qq] = 0.f;

    // ---- prologue ----
    ISSUE(0, 0);
    CP_WAIT0();
    __syncthreads();

    for (int kt = 0; kt < NKT; kt++) {
        const int cur = kt & 1;
        if (kt + 1 < NKT) ISSUE(kt + 1, cur ^ 1);

        const uint32_t* Aw = (const uint32_t*)(As + cur*ASTG + tg*KROW + wm*64 + g);
        const uint32_t* Bw = (const uint32_t*)(Bs + cur*ASTG + tg*KROW + wn*64 + g);

        COMPUTE_KS(0);
        COMPUTE_KS(1);
        COMPUTE_KS(2);
        COMPUTE_KS(3);

        if (kt + 1 < NKT) {
            CP_WAIT0();
            __syncthreads();
        }
    }

    // ---- epilogue ----
    float* ob = out + (size_t)b * O_ * NPIX;
    #pragma unroll
    for (int mi = 0; mi < 4; mi++) {
        const int r0 = tile_m*128 + wm*64 + mi*16 + g;
        #pragma unroll
        for (int ni = 0; ni < 8; ni++) {
            const int cb = nBase + wn*64 + ni*8 + 2*tg;
            if (cb < NPIX) {
                *(float2*)(ob + (size_t)r0*NPIX + cb)     = make_float2(acc[mi][ni][0], acc[mi][ni][1]);
                *(float2*)(ob + (size_t)(r0+8)*NPIX + cb) = make_float2(acc[mi][ni][2], acc[mi][ni][3]);
            }
        }
    }
    #undef ISSUE
    #undef COMPUTE_KS
}

#define CONV_SMEM (4*ASTG*4)   // 69632 B -> 3 CTAs/SM (209 KB)

// ===========================================================================
extern "C" void kernel_launch(void* const* d_in, const int* in_sizes, int n_in,
                              void* d_out, int out_size) {
    const float* x       = (const float*)d_in[0];
    const float* experts = (const float*)d_in[1];
    const float* rw1     = (const float*)d_in[2];
    const float* rb1     = (const float*)d_in[3];
    const float* rw2     = (const float*)d_in[4];
    const float* rb2     = (const float*)d_in[5];
    float* out           = (float*)d_out;

    static bool attr_set = false;
    if (!attr_set) {
        cudaFuncSetAttribute(conv_mma_kernel,
                             cudaFuncAttributeMaxDynamicSharedMemorySize, CONV_SMEM);
        attr_set = true;
    }

    pad_pool_kernel<<<dim3(C_, B_), 128>>>(x);
    mlp_kernel<<<B_, 64>>>(rw1, rb1, rw2, rb2);
    combine_kernel<<<dim3(2*NKT, B_), 256>>>(experts);
    conv_mma_kernel<<<dim3(NTILES, 2, B_), 128, CONV_SMEM>>>(out);
}